// round 14
// baseline (speedup 1.0000x reference)
#include <cuda_runtime.h>
#include <cuda_fp16.h>
#include <math.h>
#include <stdint.h>

#define BBATCH 2
#define SS 2048
#define DD 2048
#define HH 16
#define DHH 128
#define FFD 5632
#define MM (BBATCH * SS)
#define QKVN (3 * DD)        // 6144
#define F13N (2 * FFD)       // 11264

typedef __half h16;

// ------------------------- scratch (device globals) -------------------------
__device__ h16   g_xb   [(long long)MM * DD];
__device__ h16   g_wqkvT[(long long)QKVN * DD];
__device__ h16   g_woT  [(long long)DD * DD];
__device__ h16   g_w13T [(long long)F13N * DD];   // interleaved: row 2j = w1_j, 2j+1 = w3_j
__device__ h16   g_w2T  [(long long)DD * FFD];
__device__ h16   g_qb   [(long long)MM * DD];
__device__ h16   g_kb   [(long long)MM * DD];
__device__ h16   g_vb   [(long long)MM * DD];
__device__ h16   g_attnb[(long long)MM * DD];
__device__ float g_h    [(long long)MM * DD];
__device__ h16   g_yb   [(long long)MM * DD];
__device__ h16   g_gb   [(long long)MM * FFD];

// ------------------------- helpers ------------------------------------------
__device__ __forceinline__ uint32_t smem_u32(const void* p) {
    uint32_t a;
    asm("{ .reg .u64 t; cvta.to.shared.u64 t, %1; cvt.u32.u64 %0, t; }" : "=r"(a) : "l"(p));
    return a;
}

__device__ __forceinline__ void cp_async16(uint32_t dst, const void* src) {
    asm volatile("cp.async.cg.shared.global [%0], [%1], 16;" :: "r"(dst), "l"(src));
}
__device__ __forceinline__ void cp_commit() {
    asm volatile("cp.async.commit_group;");
}
__device__ __forceinline__ void cp_wait1() {
    asm volatile("cp.async.wait_group 1;");
}
__device__ __forceinline__ void cp_wait0() {
    asm volatile("cp.async.wait_group 0;");
}

__device__ __forceinline__ void ldmx4(uint32_t* r, uint32_t addr) {
    asm volatile("ldmatrix.sync.aligned.m8n8.x4.shared.b16 {%0,%1,%2,%3}, [%4];"
                 : "=r"(r[0]), "=r"(r[1]), "=r"(r[2]), "=r"(r[3]) : "r"(addr));
}
__device__ __forceinline__ void ldmx4t(uint32_t* r, uint32_t addr) {
    asm volatile("ldmatrix.sync.aligned.m8n8.x4.trans.shared.b16 {%0,%1,%2,%3}, [%4];"
                 : "=r"(r[0]), "=r"(r[1]), "=r"(r[2]), "=r"(r[3]) : "r"(addr));
}
__device__ __forceinline__ void mma16816(float* c, const uint32_t* a, const uint32_t* b) {
    asm volatile(
        "mma.sync.aligned.m16n8k16.row.col.f32.f16.f16.f32 "
        "{%0,%1,%2,%3}, {%4,%5,%6,%7}, {%8,%9}, {%0,%1,%2,%3};"
        : "+f"(c[0]), "+f"(c[1]), "+f"(c[2]), "+f"(c[3])
        : "r"(a[0]), "r"(a[1]), "r"(a[2]), "r"(a[3]), "r"(b[0]), "r"(b[1]));
}
__device__ __forceinline__ uint32_t packh2(float a, float b) {
    __half2 h = __floats2half2_rn(a, b);
    return *reinterpret_cast<uint32_t*>(&h);
}
__device__ __forceinline__ float siluf(float a) {
    return a / (1.0f + __expf(-a));
}

// ------------------------- HGEMM (mma.sync) ----------------------------------
// C[m][n] = alpha * sum_k A[m][k]*B[n][k]. A/B K-major fp16.
// mode 0: fp32 out (+Res); mode 2: silu-pair fp16 out; mode 3: QKV rope epilogue
__device__ __forceinline__ void stage_load(uint32_t sdst, const h16* g, int row0,
                                           long long ld, int k0, int tid)
{
    const int r = tid >> 1;
    const int cb = (tid & 1) * 4;
    const h16* grow = g + (long long)(row0 + r) * ld + k0;
#pragma unroll
    for (int i = 0; i < 4; i++) {
        int c = cb + i;
        uint32_t dst = sdst + (uint32_t)(r * 128 + ((c ^ (r & 7)) * 16));
        cp_async16(dst, grow + c * 8);
    }
}

#define SM_SCALE 0.08838834764831845f

__global__ __launch_bounds__(256, 2)
void hgemm(const h16* __restrict__ A, const h16* __restrict__ B,
           const float* __restrict__ Res, float* __restrict__ C,
           h16* __restrict__ C16, h16* __restrict__ O2, h16* __restrict__ O3,
           const float* __restrict__ FC, const float* __restrict__ FS,
           int M, int N, int K,
           long long lda, long long ldb, long long ldc, long long ldres,
           float alpha, int mode)
{
    extern __shared__ char smem[];

    const int m0 = blockIdx.y * 128;
    const int n0 = blockIdx.x * 128;

    const int tid = threadIdx.x;
    const int lane = tid & 31;
    const int wid = tid >> 5;
    const int wm = wid >> 2;
    const int wn = wid & 3;

    const uint32_t sb = smem_u32(smem);
    const int KT = K >> 6;

    const int nPro = (KT < 2) ? KT : 2;
    for (int s = 0; s < nPro; s++) {
        uint32_t base = sb + (uint32_t)(s % 3) * 32768u;
        stage_load(base, A, m0, lda, s * 64, tid);
        stage_load(base + 16384u, B, n0, ldb, s * 64, tid);
        cp_commit();
    }

    float acc[4][4][4];
#pragma unroll
    for (int i = 0; i < 4; i++)
#pragma unroll
        for (int j = 0; j < 4; j++)
#pragma unroll
            for (int q = 0; q < 4; q++) acc[i][j][q] = 0.0f;

    const int aRow = wm * 64 + (lane & 15);
    const int aKsel = lane >> 4;
    const int aSwz = aRow & 7;
    const int bRow7 = lane & 7;
    const int bKsel = (lane >> 3) & 1;
    const int bNtSel = (lane >> 4) & 1;

    for (int s = 0; s < KT; s++) {
        cp_wait1();
        __syncthreads();            // single barrier per stage
        if (s + 2 < KT) {
            uint32_t base = sb + (uint32_t)((s + 2) % 3) * 32768u;
            stage_load(base, A, m0, lda, (s + 2) * 64, tid);
            stage_load(base + 16384u, B, n0, ldb, (s + 2) * 64, tid);
        }
        cp_commit();

        const uint32_t base = sb + (uint32_t)(s % 3) * 32768u;
#pragma unroll
        for (int kc = 0; kc < 4; kc++) {
            uint32_t a[4][4], b[2][4];
#pragma unroll
            for (int mt = 0; mt < 4; mt++) {
                uint32_t ad = base + (uint32_t)((aRow + mt * 16) * 128 +
                              (((kc * 2 + aKsel) ^ aSwz) * 16));
                ldmx4(a[mt], ad);
            }
#pragma unroll
            for (int ntp = 0; ntp < 2; ntp++) {
                int nRow = wn * 32 + (ntp * 2 + bNtSel) * 8 + bRow7;
                uint32_t bd = base + 16384u + (uint32_t)(nRow * 128 +
                              (((kc * 2 + bKsel) ^ (nRow & 7)) * 16));
                ldmx4(b[ntp], bd);
            }
#pragma unroll
            for (int mt = 0; mt < 4; mt++) {
                mma16816(acc[mt][0], a[mt], b[0]);
                mma16816(acc[mt][1], a[mt], b[0] + 2);
                mma16816(acc[mt][2], a[mt], b[1]);
                mma16816(acc[mt][3], a[mt], b[1] + 2);
            }
        }
    }
    __syncthreads();

#pragma unroll
    for (int mt = 0; mt < 4; mt++) {
#pragma unroll
        for (int nt = 0; nt < 4; nt++) {
            const int m = m0 + wm * 64 + mt * 16 + (lane >> 2);
            const int n = n0 + wn * 32 + nt * 8 + (lane & 3) * 2;
            if (mode == 3) {
                const int i = (n & 127) >> 1;
                if (n < 2 * DD) {
                    const bool isQ = (n < DD);
                    h16* dst = isQ ? C16 : O2;
                    const float sc = isQ ? SM_SCALE : 1.0f;
                    const int ncol = n & (DD - 1);
                    const int s1 = m & (SS - 1);
                    const int s2 = (m + 8) & (SS - 1);
                    const float c1 = FC[s1 * 64 + i], sn1 = FS[s1 * 64 + i];
                    const float c2 = FC[s2 * 64 + i], sn2 = FS[s2 * 64 + i];
                    uint32_t h0 = packh2((acc[mt][nt][0] * c1 - acc[mt][nt][1] * sn1) * sc,
                                         (acc[mt][nt][0] * sn1 + acc[mt][nt][1] * c1) * sc);
                    uint32_t h1 = packh2((acc[mt][nt][2] * c2 - acc[mt][nt][3] * sn2) * sc,
                                         (acc[mt][nt][2] * sn2 + acc[mt][nt][3] * c2) * sc);
                    *reinterpret_cast<uint32_t*>(&dst[(long long)m * DD + ncol]) = h0;
                    *reinterpret_cast<uint32_t*>(&dst[(long long)(m + 8) * DD + ncol]) = h1;
                } else {
                    const int ncol = n - 2 * DD;
                    uint32_t h0 = packh2(acc[mt][nt][0], acc[mt][nt][1]);
                    uint32_t h1 = packh2(acc[mt][nt][2], acc[mt][nt][3]);
                    *reinterpret_cast<uint32_t*>(&O3[(long long)m * DD + ncol]) = h0;
                    *reinterpret_cast<uint32_t*>(&O3[(long long)(m + 8) * DD + ncol]) = h1;
                }
            } else if (mode == 2) {
                const int j = n >> 1;
                float g0 = siluf(acc[mt][nt][0]) * acc[mt][nt][1];
                float g1 = siluf(acc[mt][nt][2]) * acc[mt][nt][3];
                float g0p = __shfl_xor_sync(0xffffffffu, g0, 1);
                float g1p = __shfl_xor_sync(0xffffffffu, g1, 1);
                if (!(lane & 1)) {
                    *reinterpret_cast<uint32_t*>(&C16[(long long)m * ldc + j]) = packh2(g0, g0p);
                    *reinterpret_cast<uint32_t*>(&C16[(long long)(m + 8) * ldc + j]) = packh2(g1, g1p);
                }
            } else {
                float2 v0, v1;
                v0.x = acc[mt][nt][0] * alpha; v0.y = acc[mt][nt][1] * alpha;
                v1.x = acc[mt][nt][2] * alpha; v1.y = acc[mt][nt][3] * alpha;
                if (Res) {
                    float2 r0 = *reinterpret_cast<const float2*>(&Res[(long long)m * ldres + n]);
                    float2 r1 = *reinterpret_cast<const float2*>(&Res[(long long)(m + 8) * ldres + n]);
                    v0.x += r0.x; v0.y += r0.y; v1.x += r1.x; v1.y += r1.y;
                }
                *reinterpret_cast<float2*>(&C[(long long)m * ldc + n]) = v0;
                *reinterpret_cast<float2*>(&C[(long long)(m + 8) * ldc + n]) = v1;
            }
        }
    }
}

// ------------------------- fused flash attention ------------------------------
// 1-D grid of 512: LPT schedule — all heaviest (qt=15) tiles first across bh.
// Diagonal tiles skip fully-masked 16-key chunks (ntp/kc > wid).
#define FA_SMEM (32768 + 2 * 65536)

__global__ __launch_bounds__(256, 1)
void flash_attn(const h16* __restrict__ qg, const h16* __restrict__ kg,
                const h16* __restrict__ vg, h16* __restrict__ og)
{
    extern __shared__ char smem[];
    const int NQT = SS / 128;                     // 16
    const int idx = blockIdx.x;
    const int qt = (NQT - 1) - (idx >> 5);        // heavy first, 32 bh per qt band
    const int bh = idx & 31;
    const int b = bh >> 4, h = bh & 15;

    const h16* qp = qg + (long long)b * SS * DD + h * DHH;
    const h16* kp = kg + (long long)b * SS * DD + h * DHH;
    const h16* vp = vg + (long long)b * SS * DD + h * DHH;

    const int tid = threadIdx.x;
    const int lane = tid & 31;
    const int wid = tid >> 5;
    const int wrow = wid * 16;

    const uint32_t sb = smem_u32(smem);
    const uint32_t qbs = sb;

    stage_load(qbs, qp, qt * 128, DD, 0, tid);
    stage_load(qbs + 16384u, qp, qt * 128, DD, 64, tid);
    cp_commit();
    {
        uint32_t kvb = sb + 32768u;
        stage_load(kvb, kp, 0, DD, 0, tid);
        stage_load(kvb + 16384u, kp, 0, DD, 64, tid);
        stage_load(kvb + 32768u, vp, 0, DD, 0, tid);
        stage_load(kvb + 49152u, vp, 0, DD, 64, tid);
        cp_commit();
    }

    const int aRow = wrow + (lane & 15);
    const int aKsel = lane >> 4;
    const int aSwz = aRow & 7;
    const int bRow7 = lane & 7;
    const int bNtSel = (lane >> 4) & 1;
    const int bKsel = (lane >> 3) & 1;
    const int kvRowBase = (lane & 7) + ((lane >> 3) & 1) * 8;
    const int dSel = (lane >> 4) ? 8 : 0;

    uint32_t aq[8][4];
    float o[16][4];
    float mrow[2], lrow[2];
#pragma unroll
    for (int i = 0; i < 16; i++)
#pragma unroll
        for (int j = 0; j < 4; j++) o[i][j] = 0.0f;
    mrow[0] = mrow[1] = -1e30f;
    lrow[0] = lrow[1] = 0.0f;

    const int nKT = qt + 1;
    for (int kt = 0; kt < nKT; kt++) {
        cp_wait0();
        __syncthreads();
        const uint32_t kvb = sb + 32768u + (uint32_t)(kt & 1) * 65536u;
        if (kt + 1 < nKT) {
            uint32_t nb = sb + 32768u + (uint32_t)((kt + 1) & 1) * 65536u;
            stage_load(nb, kp, (kt + 1) * 128, DD, 0, tid);
            stage_load(nb + 16384u, kp, (kt + 1) * 128, DD, 64, tid);
            stage_load(nb + 32768u, vp, (kt + 1) * 128, DD, 0, tid);
            stage_load(nb + 49152u, vp, (kt + 1) * 128, DD, 64, tid);
            cp_commit();
        }
        if (kt == 0) {
#pragma unroll
            for (int kc = 0; kc < 8; kc++) {
                uint32_t base = qbs + (kc >= 4 ? 16384u : 0u);
                uint32_t ad = base + (uint32_t)(aRow * 128 +
                              ((((kc & 3) * 2 + aKsel) ^ aSwz) * 16));
                ldmx4(aq[kc], ad);
            }
        }

        const bool diag = (kt == qt);

        float s[16][4];
#pragma unroll
        for (int i = 0; i < 16; i++)
#pragma unroll
            for (int j = 0; j < 4; j++) s[i][j] = 0.0f;
#pragma unroll
        for (int ntp = 0; ntp < 8; ntp++) {
            if (diag && ntp > wid) break;     // fully-masked key chunk
#pragma unroll
            for (int kc = 0; kc < 8; kc++) {
                uint32_t base = kvb + (kc >= 4 ? 16384u : 0u);
                int nRow = (ntp * 2 + bNtSel) * 8 + bRow7;
                uint32_t bd = base + (uint32_t)(nRow * 128 +
                              ((((kc & 3) * 2 + bKsel) ^ (nRow & 7)) * 16));
                uint32_t bv[4];
                ldmx4(bv, bd);
                mma16816(s[ntp * 2],     aq[kc], bv);
                mma16816(s[ntp * 2 + 1], aq[kc], bv + 2);
            }
        }

        if (diag) {
            const int ii0 = wrow + (lane >> 2);
#pragma unroll
            for (int nt = 0; nt < 16; nt++) {
                int jj = nt * 8 + 2 * (lane & 3);
                if (jj > ii0)      s[nt][0] = -1e30f;
                if (jj + 1 > ii0)  s[nt][1] = -1e30f;
                if (jj > ii0 + 8)     s[nt][2] = -1e30f;
                if (jj + 1 > ii0 + 8) s[nt][3] = -1e30f;
            }
        }

        float mx0 = -1e30f, mx1 = -1e30f;
#pragma unroll
        for (int nt = 0; nt < 16; nt++) {
            mx0 = fmaxf(mx0, fmaxf(s[nt][0], s[nt][1]));
            mx1 = fmaxf(mx1, fmaxf(s[nt][2], s[nt][3]));
        }
        mx0 = fmaxf(mx0, __shfl_xor_sync(0xffffffffu, mx0, 1));
        mx0 = fmaxf(mx0, __shfl_xor_sync(0xffffffffu, mx0, 2));
        mx1 = fmaxf(mx1, __shfl_xor_sync(0xffffffffu, mx1, 1));
        mx1 = fmaxf(mx1, __shfl_xor_sync(0xffffffffu, mx1, 2));
        const float mn0 = fmaxf(mrow[0], mx0);
        const float mn1 = fmaxf(mrow[1], mx1);
        const float f0 = __expf(mrow[0] - mn0);
        const float f1 = __expf(mrow[1] - mn1);
        mrow[0] = mn0; mrow[1] = mn1;
#pragma unroll
        for (int nt = 0; nt < 16; nt++) {
            o[nt][0] *= f0; o[nt][1] *= f0;
            o[nt][2] *= f1; o[nt][3] *= f1;
        }
        float sum0 = 0.0f, sum1 = 0.0f;
#pragma unroll
        for (int nt = 0; nt < 16; nt++) {
            s[nt][0] = __expf(s[nt][0] - mn0);
            s[nt][1] = __expf(s[nt][1] - mn0);
            s[nt][2] = __expf(s[nt][2] - mn1);
            s[nt][3] = __expf(s[nt][3] - mn1);
            sum0 += s[nt][0] + s[nt][1];
            sum1 += s[nt][2] + s[nt][3];
        }
        sum0 += __shfl_xor_sync(0xffffffffu, sum0, 1);
        sum0 += __shfl_xor_sync(0xffffffffu, sum0, 2);
        sum1 += __shfl_xor_sync(0xffffffffu, sum1, 1);
        sum1 += __shfl_xor_sync(0xffffffffu, sum1, 2);
        lrow[0] = lrow[0] * f0 + sum0;
        lrow[1] = lrow[1] * f1 + sum1;

#pragma unroll
        for (int kc = 0; kc < 8; kc++) {
            if (diag && kc > wid) break;      // P fragments all zero
            uint32_t ap[4];
            ap[0] = packh2(s[kc * 2][0], s[kc * 2][1]);
            ap[1] = packh2(s[kc * 2][2], s[kc * 2][3]);
            ap[2] = packh2(s[kc * 2 + 1][0], s[kc * 2 + 1][1]);
            ap[3] = packh2(s[kc * 2 + 1][2], s[kc * 2 + 1][3]);
            const int kvRow = kc * 16 + kvRowBase;
            const uint32_t rowBase = kvb + 32768u + (uint32_t)(kvRow * 128);
            const uint32_t swz = (uint32_t)(kvRow & 7);
#pragma unroll
            for (int ntp = 0; ntp < 8; ntp++) {
                const int d0 = ntp * 16;
                const uint32_t sub = (d0 >= 64) ? 16384u : 0u;
                const int c8 = ((d0 & 63) + dSel) >> 3;
                uint32_t bd = rowBase + sub + (uint32_t)(((uint32_t)c8 ^ swz) * 16);
                uint32_t bv[4];
                ldmx4t(bv, bd);
                mma16816(o[ntp * 2],     ap, bv);
                mma16816(o[ntp * 2 + 1], ap, bv + 2);
            }
        }
    }

    const float inv0 = 1.0f / lrow[0];
    const float inv1 = 1.0f / lrow[1];
    const long long row0 = (long long)b * SS + qt * 128 + wrow + (lane >> 2);
#pragma unroll
    for (int nt = 0; nt < 16; nt++) {
        int dcol = h * DHH + nt * 8 + 2 * (lane & 3);
        uint32_t h0 = packh2(o[nt][0] * inv0, o[nt][1] * inv0);
        uint32_t h1 = packh2(o[nt][2] * inv1, o[nt][3] * inv1);
        *reinterpret_cast<uint32_t*>(&og[row0 * DD + dcol]) = h0;
        *reinterpret_cast<uint32_t*>(&og[(row0 + 8) * DD + dcol]) = h1;
    }
}

// ------------------------- elementwise kernels --------------------------------
__global__ __launch_bounds__(256)
void rmsnorm_h16(const float* __restrict__ in, const float* __restrict__ w,
                 h16* __restrict__ o)
{
    __shared__ float red[256];
    const long long row = blockIdx.x;
    const float4* p = reinterpret_cast<const float4*>(in + row * DD);
    const float4* wp = reinterpret_cast<const float4*>(w);
    const int tid = threadIdx.x;
    float4 v[2];
    v[0] = p[tid];
    v[1] = p[tid + 256];
    float ss = v[0].x * v[0].x + v[0].y * v[0].y + v[0].z * v[0].z + v[0].w * v[0].w
             + v[1].x * v[1].x + v[1].y * v[1].y + v[1].z * v[1].z + v[1].w * v[1].w;
    red[tid] = ss;
    __syncthreads();
    for (int s = 128; s > 0; s >>= 1) {
        if (tid < s) red[tid] += red[tid + s];
        __syncthreads();
    }
    const float scale = rsqrtf(red[0] / (float)DD + 1e-6f);
    uint32_t* op = reinterpret_cast<uint32_t*>(o + row * DD);
#pragma unroll
    for (int t = 0; t < 2; t++) {
        const int j4 = tid + t * 256;
        const float4 ww = wp[j4];
        op[j4 * 2]     = packh2(v[t].x * scale * ww.x, v[t].y * scale * ww.y);
        op[j4 * 2 + 1] = packh2(v[t].z * scale * ww.z, v[t].w * scale * ww.w);
    }
}

// W [K,N] fp32 -> WT row (n*rowMul + rowOff) of [*, K] fp16
__global__ __launch_bounds__(256)
void transpose_h16(const float* __restrict__ W, h16* __restrict__ out, int K, int N,
                   int rowMul, int rowOff)
{
    __shared__ float t[32][33];
    const int k0 = blockIdx.y * 32, n0 = blockIdx.x * 32;
    const int tx = threadIdx.x & 31, ty = threadIdx.x >> 5;
#pragma unroll
    for (int i = 0; i < 32; i += 8)
        t[ty + i][tx] = W[(long long)(k0 + ty + i) * N + n0 + tx];
    __syncthreads();
#pragma unroll
    for (int i = 0; i < 32; i += 8)
        out[(long long)((n0 + ty + i) * rowMul + rowOff) * K + k0 + tx] =
            __float2half_rn(t[tx][ty + i]);
}

// ------------------------- host ----------------------------------------------
#define GEMM_SMEM (3 * 32768)

static void gemm(const h16* A, const h16* B, const float* Res, float* C,
                 h16* C16, h16* O2, h16* O3, const float* FC, const float* FS,
                 int M, int N, int K,
                 long long lda, long long ldb, long long ldc, long long ldres,
                 float alpha, int mode, cudaStream_t st)
{
    dim3 grid(N / 128, M / 128, 1);
    hgemm<<<grid, 256, GEMM_SMEM, st>>>(A, B, Res, C, C16, O2, O3, FC, FS,
                                        M, N, K, lda, ldb, ldc, ldres, alpha, mode);
}

extern "C" void kernel_launch(void* const* d_in, const int* in_sizes, int n_in,
                              void* d_out, int out_size)
{
    (void)in_sizes; (void)n_in; (void)out_size;
    const float* hidden = (const float*)d_in[0];
    const float* fcos   = (const float*)d_in[1];
    const float* fsin   = (const float*)d_in[2];
    const float* wq     = (const float*)d_in[3];
    const float* wk     = (const float*)d_in[4];
    const float* wv     = (const float*)d_in[5];
    const float* wo     = (const float*)d_in[6];
    const float* w1     = (const float*)d_in[7];
    const float* w2     = (const float*)d_in[8];
    const float* w3     = (const float*)d_in[9];
    const float* anw    = (const float*)d_in[10];
    const float* fnw    = (const float*)d_in[11];
    float* out = (float*)d_out;

    static cudaStream_t s2 = nullptr;
    static cudaEvent_t evF = nullptr, evA = nullptr, evW = nullptr, evB = nullptr;
    if (s2 == nullptr) {
        cudaStreamCreateWithFlags(&s2, cudaStreamNonBlocking);
        cudaEventCreateWithFlags(&evF, cudaEventDisableTiming);
        cudaEventCreateWithFlags(&evA, cudaEventDisableTiming);
        cudaEventCreateWithFlags(&evW, cudaEventDisableTiming);
        cudaEventCreateWithFlags(&evB, cudaEventDisableTiming);
    }

    cudaFuncSetAttribute(hgemm, cudaFuncAttributeMaxDynamicSharedMemorySize, GEMM_SMEM);
    cudaFuncSetAttribute(flash_attn, cudaFuncAttributeMaxDynamicSharedMemorySize, FA_SMEM);

    h16 *xb, *wqkvT, *woT, *w13T, *w2T, *qb, *kb, *vb, *attnb, *yb, *gb;
    float *h;
    cudaGetSymbolAddress((void**)&xb,    g_xb);
    cudaGetSymbolAddress((void**)&wqkvT, g_wqkvT);
    cudaGetSymbolAddress((void**)&woT,   g_woT);
    cudaGetSymbolAddress((void**)&w13T,  g_w13T);
    cudaGetSymbolAddress((void**)&w2T,   g_w2T);
    cudaGetSymbolAddress((void**)&qb,    g_qb);
    cudaGetSymbolAddress((void**)&kb,    g_kb);
    cudaGetSymbolAddress((void**)&vb,    g_vb);
    cudaGetSymbolAddress((void**)&attnb, g_attnb);
    cudaGetSymbolAddress((void**)&h,     g_h);
    cudaGetSymbolAddress((void**)&yb,    g_yb);
    cudaGetSymbolAddress((void**)&gb,    g_gb);

    // ---- main: rmsnorm first (no deps on weight prep)
    rmsnorm_h16<<<MM, 256>>>(hidden, anw, xb);

    // ---- fork side stream: wq/wk transposes; wv on main (overlaps s2)
    cudaEventRecord(evF, 0);
    cudaStreamWaitEvent(s2, evF, 0);
    { dim3 g(DD / 32, DD / 32);
      transpose_h16<<<g, 256, 0, s2>>>(wq, wqkvT,                          DD, DD, 1, 0);
      transpose_h16<<<g, 256, 0, s2>>>(wk, wqkvT + (long long)DD * DD,     DD, DD, 1, 0); }
    cudaEventRecord(evA, s2);
    { dim3 g(DD / 32, DD / 32);
      transpose_h16<<<g, 256>>>(wv, wqkvT + (long long)2 * DD * DD, DD, DD, 1, 0); }

    cudaStreamWaitEvent(0, evA, 0);
    // qkv GEMM with fused rope epilogue -> qb (roped+scaled), kb (roped), vb
    gemm(xb, wqkvT, nullptr, nullptr, qb, kb, vb, fcos, fsin,
         MM, QKVN, DD, DD, DD, DD, 0, 1.0f, 3, 0);

    // fused flash attention (LPT 1-D grid, diagonal skip) -> attnb fp16
    flash_attn<<<(SS / 128) * BBATCH * HH, 256, FA_SMEM>>>(qb, kb, vb, attnb);

    // ---- remaining weight prep on s2 (overlaps qkv/attention)
    { dim3 g(DD / 32, DD / 32);
      transpose_h16<<<g, 256, 0, s2>>>(wo, woT, DD, DD, 1, 0); }
    cudaEventRecord(evW, s2);
    { dim3 g(FFD / 32, DD / 32);
      transpose_h16<<<g, 256, 0, s2>>>(w1, w13T, DD, FFD, 2, 0);   // even rows
      transpose_h16<<<g, 256, 0, s2>>>(w3, w13T, DD, FFD, 2, 1); } // odd rows
    { dim3 g(DD / 32, FFD / 32);
      transpose_h16<<<g, 256, 0, s2>>>(w2, w2T, FFD, DD, 1, 0); }
    cudaEventRecord(evB, s2);

    cudaStreamWaitEvent(0, evW, 0);
    // h = hidden + attn @ wo
    gemm(attnb, woT, hidden, h, nullptr, nullptr, nullptr, nullptr, nullptr,
         MM, DD, DD, DD, DD, DD, DD, 1.0f, 0, 0);

    // y = rmsnorm(h) -> fp16
    rmsnorm_h16<<<MM, 256>>>(h, fnw, yb);

    cudaStreamWaitEvent(0, evB, 0);
    // g = silu(y@w1) * (y@w3) -> fp16 (fused epilogue, interleaved weights)
    gemm(yb, w13T, nullptr, nullptr, gb, nullptr, nullptr, nullptr, nullptr,
         MM, F13N, DD, DD, DD, FFD, 0, 1.0f, 2, 0);

    // out = h + g @ w2
    gemm(gb, w2T, h, out, nullptr, nullptr, nullptr, nullptr, nullptr,
         MM, DD, FFD, FFD, FFD, DD, DD, 1.0f, 0, 0);
}

// round 15
// speedup vs baseline: 1.0049x; 1.0049x over previous
#include <cuda_runtime.h>
#include <cuda_fp16.h>
#include <math.h>
#include <stdint.h>

#define BBATCH 2
#define SS 2048
#define DD 2048
#define HH 16
#define DHH 128
#define FFD 5632
#define MM (BBATCH * SS)
#define QKVN (3 * DD)        // 6144
#define F13N (2 * FFD)       // 11264

typedef __half h16;

// ------------------------- scratch (device globals) -------------------------
__device__ h16   g_xb   [(long long)MM * DD];
__device__ h16   g_wqkvT[(long long)QKVN * DD];
__device__ h16   g_woT  [(long long)DD * DD];
__device__ h16   g_w13T [(long long)F13N * DD];   // interleaved: row 2j = w1_j, 2j+1 = w3_j
__device__ h16   g_w2T  [(long long)DD * FFD];
__device__ h16   g_qb   [(long long)MM * DD];
__device__ h16   g_kb   [(long long)MM * DD];
__device__ h16   g_vb   [(long long)MM * DD];
__device__ h16   g_attnb[(long long)MM * DD];
__device__ float g_h    [(long long)MM * DD];
__device__ h16   g_yb   [(long long)MM * DD];
__device__ h16   g_gb   [(long long)MM * FFD];

// ------------------------- helpers ------------------------------------------
__device__ __forceinline__ uint32_t smem_u32(const void* p) {
    uint32_t a;
    asm("{ .reg .u64 t; cvta.to.shared.u64 t, %1; cvt.u32.u64 %0, t; }" : "=r"(a) : "l"(p));
    return a;
}

__device__ __forceinline__ void cp_async16(uint32_t dst, const void* src) {
    asm volatile("cp.async.cg.shared.global [%0], [%1], 16;" :: "r"(dst), "l"(src));
}
__device__ __forceinline__ void cp_commit() {
    asm volatile("cp.async.commit_group;");
}
__device__ __forceinline__ void cp_wait1() {
    asm volatile("cp.async.wait_group 1;");
}
__device__ __forceinline__ void cp_wait0() {
    asm volatile("cp.async.wait_group 0;");
}

__device__ __forceinline__ void ldmx4(uint32_t* r, uint32_t addr) {
    asm volatile("ldmatrix.sync.aligned.m8n8.x4.shared.b16 {%0,%1,%2,%3}, [%4];"
                 : "=r"(r[0]), "=r"(r[1]), "=r"(r[2]), "=r"(r[3]) : "r"(addr));
}
__device__ __forceinline__ void ldmx4t(uint32_t* r, uint32_t addr) {
    asm volatile("ldmatrix.sync.aligned.m8n8.x4.trans.shared.b16 {%0,%1,%2,%3}, [%4];"
                 : "=r"(r[0]), "=r"(r[1]), "=r"(r[2]), "=r"(r[3]) : "r"(addr));
}
__device__ __forceinline__ void mma16816(float* c, const uint32_t* a, const uint32_t* b) {
    asm volatile(
        "mma.sync.aligned.m16n8k16.row.col.f32.f16.f16.f32 "
        "{%0,%1,%2,%3}, {%4,%5,%6,%7}, {%8,%9}, {%0,%1,%2,%3};"
        : "+f"(c[0]), "+f"(c[1]), "+f"(c[2]), "+f"(c[3])
        : "r"(a[0]), "r"(a[1]), "r"(a[2]), "r"(a[3]), "r"(b[0]), "r"(b[1]));
}
__device__ __forceinline__ uint32_t packh2(float a, float b) {
    __half2 h = __floats2half2_rn(a, b);
    return *reinterpret_cast<uint32_t*>(&h);
}
__device__ __forceinline__ float siluf(float a) {
    return a / (1.0f + __expf(-a));
}

// ------------------------- HGEMM (mma.sync) ----------------------------------
// C[m][n] = alpha * sum_k A[m][k]*B[n][k]. A/B K-major fp16.
// mode 0: fp32 out (+Res); mode 2: silu-pair fp16 out; mode 3: QKV rope epilogue
__device__ __forceinline__ void stage_load(uint32_t sdst, const h16* g, int row0,
                                           long long ld, int k0, int tid)
{
    const int r = tid >> 1;
    const int cb = (tid & 1) * 4;
    const h16* grow = g + (long long)(row0 + r) * ld + k0;
#pragma unroll
    for (int i = 0; i < 4; i++) {
        int c = cb + i;
        uint32_t dst = sdst + (uint32_t)(r * 128 + ((c ^ (r & 7)) * 16));
        cp_async16(dst, grow + c * 8);
    }
}

#define SM_SCALE 0.08838834764831845f

__global__ __launch_bounds__(256, 2)
void hgemm(const h16* __restrict__ A, const h16* __restrict__ B,
           const float* __restrict__ Res, float* __restrict__ C,
           h16* __restrict__ C16, h16* __restrict__ O2, h16* __restrict__ O3,
           const float* __restrict__ FC, const float* __restrict__ FS,
           int M, int N, int K,
           long long lda, long long ldb, long long ldc, long long ldres,
           float alpha, int mode)
{
    extern __shared__ char smem[];

    const int m0 = blockIdx.y * 128;
    const int n0 = blockIdx.x * 128;

    const int tid = threadIdx.x;
    const int lane = tid & 31;
    const int wid = tid >> 5;
    const int wm = wid >> 2;
    const int wn = wid & 3;

    const uint32_t sb = smem_u32(smem);
    const int KT = K >> 6;

    const int nPro = (KT < 2) ? KT : 2;
    for (int s = 0; s < nPro; s++) {
        uint32_t base = sb + (uint32_t)(s % 3) * 32768u;
        stage_load(base, A, m0, lda, s * 64, tid);
        stage_load(base + 16384u, B, n0, ldb, s * 64, tid);
        cp_commit();
    }

    float acc[4][4][4];
#pragma unroll
    for (int i = 0; i < 4; i++)
#pragma unroll
        for (int j = 0; j < 4; j++)
#pragma unroll
            for (int q = 0; q < 4; q++) acc[i][j][q] = 0.0f;

    const int aRow = wm * 64 + (lane & 15);
    const int aKsel = lane >> 4;
    const int aSwz = aRow & 7;
    const int bRow7 = lane & 7;
    const int bKsel = (lane >> 3) & 1;
    const int bNtSel = (lane >> 4) & 1;

    for (int s = 0; s < KT; s++) {
        cp_wait1();
        __syncthreads();            // single barrier per stage
        if (s + 2 < KT) {
            uint32_t base = sb + (uint32_t)((s + 2) % 3) * 32768u;
            stage_load(base, A, m0, lda, (s + 2) * 64, tid);
            stage_load(base + 16384u, B, n0, ldb, (s + 2) * 64, tid);
        }
        cp_commit();

        const uint32_t base = sb + (uint32_t)(s % 3) * 32768u;
#pragma unroll
        for (int kc = 0; kc < 4; kc++) {
            uint32_t a[4][4], b[2][4];
#pragma unroll
            for (int mt = 0; mt < 4; mt++) {
                uint32_t ad = base + (uint32_t)((aRow + mt * 16) * 128 +
                              (((kc * 2 + aKsel) ^ aSwz) * 16));
                ldmx4(a[mt], ad);
            }
#pragma unroll
            for (int ntp = 0; ntp < 2; ntp++) {
                int nRow = wn * 32 + (ntp * 2 + bNtSel) * 8 + bRow7;
                uint32_t bd = base + 16384u + (uint32_t)(nRow * 128 +
                              (((kc * 2 + bKsel) ^ (nRow & 7)) * 16));
                ldmx4(b[ntp], bd);
            }
#pragma unroll
            for (int mt = 0; mt < 4; mt++) {
                mma16816(acc[mt][0], a[mt], b[0]);
                mma16816(acc[mt][1], a[mt], b[0] + 2);
                mma16816(acc[mt][2], a[mt], b[1]);
                mma16816(acc[mt][3], a[mt], b[1] + 2);
            }
        }
    }
    __syncthreads();

#pragma unroll
    for (int mt = 0; mt < 4; mt++) {
#pragma unroll
        for (int nt = 0; nt < 4; nt++) {
            const int m = m0 + wm * 64 + mt * 16 + (lane >> 2);
            const int n = n0 + wn * 32 + nt * 8 + (lane & 3) * 2;
            if (mode == 3) {
                const int i = (n & 127) >> 1;
                if (n < 2 * DD) {
                    const bool isQ = (n < DD);
                    h16* dst = isQ ? C16 : O2;
                    const float sc = isQ ? SM_SCALE : 1.0f;
                    const int ncol = n & (DD - 1);
                    const int s1 = m & (SS - 1);
                    const int s2 = (m + 8) & (SS - 1);
                    const float c1 = FC[s1 * 64 + i], sn1 = FS[s1 * 64 + i];
                    const float c2 = FC[s2 * 64 + i], sn2 = FS[s2 * 64 + i];
                    uint32_t h0 = packh2((acc[mt][nt][0] * c1 - acc[mt][nt][1] * sn1) * sc,
                                         (acc[mt][nt][0] * sn1 + acc[mt][nt][1] * c1) * sc);
                    uint32_t h1 = packh2((acc[mt][nt][2] * c2 - acc[mt][nt][3] * sn2) * sc,
                                         (acc[mt][nt][2] * sn2 + acc[mt][nt][3] * c2) * sc);
                    *reinterpret_cast<uint32_t*>(&dst[(long long)m * DD + ncol]) = h0;
                    *reinterpret_cast<uint32_t*>(&dst[(long long)(m + 8) * DD + ncol]) = h1;
                } else {
                    const int ncol = n - 2 * DD;
                    uint32_t h0 = packh2(acc[mt][nt][0], acc[mt][nt][1]);
                    uint32_t h1 = packh2(acc[mt][nt][2], acc[mt][nt][3]);
                    *reinterpret_cast<uint32_t*>(&O3[(long long)m * DD + ncol]) = h0;
                    *reinterpret_cast<uint32_t*>(&O3[(long long)(m + 8) * DD + ncol]) = h1;
                }
            } else if (mode == 2) {
                const int j = n >> 1;
                float g0 = siluf(acc[mt][nt][0]) * acc[mt][nt][1];
                float g1 = siluf(acc[mt][nt][2]) * acc[mt][nt][3];
                float g0p = __shfl_xor_sync(0xffffffffu, g0, 1);
                float g1p = __shfl_xor_sync(0xffffffffu, g1, 1);
                if (!(lane & 1)) {
                    *reinterpret_cast<uint32_t*>(&C16[(long long)m * ldc + j]) = packh2(g0, g0p);
                    *reinterpret_cast<uint32_t*>(&C16[(long long)(m + 8) * ldc + j]) = packh2(g1, g1p);
                }
            } else {
                float2 v0, v1;
                v0.x = acc[mt][nt][0] * alpha; v0.y = acc[mt][nt][1] * alpha;
                v1.x = acc[mt][nt][2] * alpha; v1.y = acc[mt][nt][3] * alpha;
                if (Res) {
                    float2 r0 = *reinterpret_cast<const float2*>(&Res[(long long)m * ldres + n]);
                    float2 r1 = *reinterpret_cast<const float2*>(&Res[(long long)(m + 8) * ldres + n]);
                    v0.x += r0.x; v0.y += r0.y; v1.x += r1.x; v1.y += r1.y;
                }
                *reinterpret_cast<float2*>(&C[(long long)m * ldc + n]) = v0;
                *reinterpret_cast<float2*>(&C[(long long)(m + 8) * ldc + n]) = v1;
            }
        }
    }
}

// ------------------------- fused flash attention ------------------------------
// 1-D grid of 512 (LPT). Mainloop kt in [0,qt) is branch-free; diagonal tile
// peeled into a separate section with wid-bounded loops (skipped work is zero).
#define FA_SMEM (32768 + 2 * 65536)

__global__ __launch_bounds__(256, 1)
void flash_attn(const h16* __restrict__ qg, const h16* __restrict__ kg,
                const h16* __restrict__ vg, h16* __restrict__ og)
{
    extern __shared__ char smem[];
    const int NQT = SS / 128;                     // 16
    const int idx = blockIdx.x;
    const int qt = (NQT - 1) - (idx >> 5);        // heavy first, 32 bh per qt band
    const int bh = idx & 31;
    const int b = bh >> 4, h = bh & 15;

    const h16* qp = qg + (long long)b * SS * DD + h * DHH;
    const h16* kp = kg + (long long)b * SS * DD + h * DHH;
    const h16* vp = vg + (long long)b * SS * DD + h * DHH;

    const int tid = threadIdx.x;
    const int lane = tid & 31;
    const int wid = tid >> 5;
    const int wrow = wid * 16;

    const uint32_t sb = smem_u32(smem);
    const uint32_t qbs = sb;

    stage_load(qbs, qp, qt * 128, DD, 0, tid);
    stage_load(qbs + 16384u, qp, qt * 128, DD, 64, tid);
    cp_commit();
    {
        uint32_t kvb = sb + 32768u;
        stage_load(kvb, kp, 0, DD, 0, tid);
        stage_load(kvb + 16384u, kp, 0, DD, 64, tid);
        stage_load(kvb + 32768u, vp, 0, DD, 0, tid);
        stage_load(kvb + 49152u, vp, 0, DD, 64, tid);
        cp_commit();
    }

    const int aRow = wrow + (lane & 15);
    const int aKsel = lane >> 4;
    const int aSwz = aRow & 7;
    const int bRow7 = lane & 7;
    const int bNtSel = (lane >> 4) & 1;
    const int bKsel = (lane >> 3) & 1;
    const int kvRowBase = (lane & 7) + ((lane >> 3) & 1) * 8;
    const int dSel = (lane >> 4) ? 8 : 0;

    uint32_t aq[8][4];
    float o[16][4];
    float mrow[2], lrow[2];
#pragma unroll
    for (int i = 0; i < 16; i++)
#pragma unroll
        for (int j = 0; j < 4; j++) o[i][j] = 0.0f;
    mrow[0] = mrow[1] = -1e30f;
    lrow[0] = lrow[1] = 0.0f;

    // ---- mainloop: off-diagonal tiles, fully unrolled bodies, no masking
    for (int kt = 0; kt < qt; kt++) {
        cp_wait0();
        __syncthreads();
        const uint32_t kvb = sb + 32768u + (uint32_t)(kt & 1) * 65536u;
        {   // successor always exists (kt+1 <= qt)
            uint32_t nb = sb + 32768u + (uint32_t)((kt + 1) & 1) * 65536u;
            stage_load(nb, kp, (kt + 1) * 128, DD, 0, tid);
            stage_load(nb + 16384u, kp, (kt + 1) * 128, DD, 64, tid);
            stage_load(nb + 32768u, vp, (kt + 1) * 128, DD, 0, tid);
            stage_load(nb + 49152u, vp, (kt + 1) * 128, DD, 64, tid);
            cp_commit();
        }
        if (kt == 0) {
#pragma unroll
            for (int kc = 0; kc < 8; kc++) {
                uint32_t base = qbs + (kc >= 4 ? 16384u : 0u);
                uint32_t ad = base + (uint32_t)(aRow * 128 +
                              ((((kc & 3) * 2 + aKsel) ^ aSwz) * 16));
                ldmx4(aq[kc], ad);
            }
        }

        float s[16][4];
#pragma unroll
        for (int i = 0; i < 16; i++)
#pragma unroll
            for (int j = 0; j < 4; j++) s[i][j] = 0.0f;
#pragma unroll
        for (int ntp = 0; ntp < 8; ntp++) {
#pragma unroll
            for (int kc = 0; kc < 8; kc++) {
                uint32_t base = kvb + (kc >= 4 ? 16384u : 0u);
                int nRow = (ntp * 2 + bNtSel) * 8 + bRow7;
                uint32_t bd = base + (uint32_t)(nRow * 128 +
                              ((((kc & 3) * 2 + bKsel) ^ (nRow & 7)) * 16));
                uint32_t bv[4];
                ldmx4(bv, bd);
                mma16816(s[ntp * 2],     aq[kc], bv);
                mma16816(s[ntp * 2 + 1], aq[kc], bv + 2);
            }
        }

        float mx0 = -1e30f, mx1 = -1e30f;
#pragma unroll
        for (int nt = 0; nt < 16; nt++) {
            mx0 = fmaxf(mx0, fmaxf(s[nt][0], s[nt][1]));
            mx1 = fmaxf(mx1, fmaxf(s[nt][2], s[nt][3]));
        }
        mx0 = fmaxf(mx0, __shfl_xor_sync(0xffffffffu, mx0, 1));
        mx0 = fmaxf(mx0, __shfl_xor_sync(0xffffffffu, mx0, 2));
        mx1 = fmaxf(mx1, __shfl_xor_sync(0xffffffffu, mx1, 1));
        mx1 = fmaxf(mx1, __shfl_xor_sync(0xffffffffu, mx1, 2));
        const float mn0 = fmaxf(mrow[0], mx0);
        const float mn1 = fmaxf(mrow[1], mx1);
        const float f0 = __expf(mrow[0] - mn0);
        const float f1 = __expf(mrow[1] - mn1);
        mrow[0] = mn0; mrow[1] = mn1;
#pragma unroll
        for (int nt = 0; nt < 16; nt++) {
            o[nt][0] *= f0; o[nt][1] *= f0;
            o[nt][2] *= f1; o[nt][3] *= f1;
        }
        float sum0 = 0.0f, sum1 = 0.0f;
#pragma unroll
        for (int nt = 0; nt < 16; nt++) {
            s[nt][0] = __expf(s[nt][0] - mn0);
            s[nt][1] = __expf(s[nt][1] - mn0);
            s[nt][2] = __expf(s[nt][2] - mn1);
            s[nt][3] = __expf(s[nt][3] - mn1);
            sum0 += s[nt][0] + s[nt][1];
            sum1 += s[nt][2] + s[nt][3];
        }
        sum0 += __shfl_xor_sync(0xffffffffu, sum0, 1);
        sum0 += __shfl_xor_sync(0xffffffffu, sum0, 2);
        sum1 += __shfl_xor_sync(0xffffffffu, sum1, 1);
        sum1 += __shfl_xor_sync(0xffffffffu, sum1, 2);
        lrow[0] = lrow[0] * f0 + sum0;
        lrow[1] = lrow[1] * f1 + sum1;

#pragma unroll
        for (int kc = 0; kc < 8; kc++) {
            uint32_t ap[4];
            ap[0] = packh2(s[kc * 2][0], s[kc * 2][1]);
            ap[1] = packh2(s[kc * 2][2], s[kc * 2][3]);
            ap[2] = packh2(s[kc * 2 + 1][0], s[kc * 2 + 1][1]);
            ap[3] = packh2(s[kc * 2 + 1][2], s[kc * 2 + 1][3]);
            const int kvRow = kc * 16 + kvRowBase;
            const uint32_t rowBase = kvb + 32768u + (uint32_t)(kvRow * 128);
            const uint32_t swz = (uint32_t)(kvRow & 7);
#pragma unroll
            for (int ntp = 0; ntp < 8; ntp++) {
                const int d0 = ntp * 16;
                const uint32_t sub = (d0 >= 64) ? 16384u : 0u;
                const int c8 = ((d0 & 63) + dSel) >> 3;
                uint32_t bd = rowBase + sub + (uint32_t)(((uint32_t)c8 ^ swz) * 16);
                uint32_t bv[4];
                ldmx4t(bv, bd);
                mma16816(o[ntp * 2],     ap, bv);
                mma16816(o[ntp * 2 + 1], ap, bv + 2);
            }
        }
    }

    // ---- peeled diagonal tile (kt == qt): wid-bounded loops
    {
        cp_wait0();
        __syncthreads();
        const uint32_t kvb = sb + 32768u + (uint32_t)(qt & 1) * 65536u;
        if (qt == 0) {
#pragma unroll
            for (int kc = 0; kc < 8; kc++) {
                uint32_t base = qbs + (kc >= 4 ? 16384u : 0u);
                uint32_t ad = base + (uint32_t)(aRow * 128 +
                              ((((kc & 3) * 2 + aKsel) ^ aSwz) * 16));
                ldmx4(aq[kc], ad);
            }
        }

        float s[16][4];
#pragma unroll
        for (int i = 0; i < 16; i++)
#pragma unroll
            for (int j = 0; j < 4; j++) s[i][j] = 0.0f;
        for (int ntp = 0; ntp <= wid; ntp++) {      // chunks beyond wid fully masked
#pragma unroll
            for (int kc = 0; kc < 8; kc++) {
                uint32_t base = kvb + (kc >= 4 ? 16384u : 0u);
                int nRow = (ntp * 2 + bNtSel) * 8 + bRow7;
                uint32_t bd = base + (uint32_t)(nRow * 128 +
                              ((((kc & 3) * 2 + bKsel) ^ (nRow & 7)) * 16));
                uint32_t bv[4];
                ldmx4(bv, bd);
                mma16816(s[ntp * 2],     aq[kc], bv);
                mma16816(s[ntp * 2 + 1], aq[kc], bv + 2);
            }
        }

        {
            const int ii0 = wrow + (lane >> 2);
#pragma unroll
            for (int nt = 0; nt < 16; nt++) {
                int jj = nt * 8 + 2 * (lane & 3);
                if (jj > ii0)      s[nt][0] = -1e30f;
                if (jj + 1 > ii0)  s[nt][1] = -1e30f;
                if (jj > ii0 + 8)     s[nt][2] = -1e30f;
                if (jj + 1 > ii0 + 8) s[nt][3] = -1e30f;
            }
        }

        float mx0 = -1e30f, mx1 = -1e30f;
#pragma unroll
        for (int nt = 0; nt < 16; nt++) {
            mx0 = fmaxf(mx0, fmaxf(s[nt][0], s[nt][1]));
            mx1 = fmaxf(mx1, fmaxf(s[nt][2], s[nt][3]));
        }
        mx0 = fmaxf(mx0, __shfl_xor_sync(0xffffffffu, mx0, 1));
        mx0 = fmaxf(mx0, __shfl_xor_sync(0xffffffffu, mx0, 2));
        mx1 = fmaxf(mx1, __shfl_xor_sync(0xffffffffu, mx1, 1));
        mx1 = fmaxf(mx1, __shfl_xor_sync(0xffffffffu, mx1, 2));
        const float mn0 = fmaxf(mrow[0], mx0);
        const float mn1 = fmaxf(mrow[1], mx1);
        const float f0 = __expf(mrow[0] - mn0);
        const float f1 = __expf(mrow[1] - mn1);
        mrow[0] = mn0; mrow[1] = mn1;
#pragma unroll
        for (int nt = 0; nt < 16; nt++) {
            o[nt][0] *= f0; o[nt][1] *= f0;
            o[nt][2] *= f1; o[nt][3] *= f1;
        }
        float sum0 = 0.0f, sum1 = 0.0f;
#pragma unroll
        for (int nt = 0; nt < 16; nt++) {
            s[nt][0] = __expf(s[nt][0] - mn0);
            s[nt][1] = __expf(s[nt][1] - mn0);
            s[nt][2] = __expf(s[nt][2] - mn1);
            s[nt][3] = __expf(s[nt][3] - mn1);
            sum0 += s[nt][0] + s[nt][1];
            sum1 += s[nt][2] + s[nt][3];
        }
        sum0 += __shfl_xor_sync(0xffffffffu, sum0, 1);
        sum0 += __shfl_xor_sync(0xffffffffu, sum0, 2);
        sum1 += __shfl_xor_sync(0xffffffffu, sum1, 1);
        sum1 += __shfl_xor_sync(0xffffffffu, sum1, 2);
        lrow[0] = lrow[0] * f0 + sum0;
        lrow[1] = lrow[1] * f1 + sum1;

        for (int kc = 0; kc <= wid; kc++) {         // P beyond wid is exactly 0
            uint32_t ap[4];
            ap[0] = packh2(s[kc * 2][0], s[kc * 2][1]);
            ap[1] = packh2(s[kc * 2][2], s[kc * 2][3]);
            ap[2] = packh2(s[kc * 2 + 1][0], s[kc * 2 + 1][1]);
            ap[3] = packh2(s[kc * 2 + 1][2], s[kc * 2 + 1][3]);
            const int kvRow = kc * 16 + kvRowBase;
            const uint32_t rowBase = kvb + 32768u + (uint32_t)(kvRow * 128);
            const uint32_t swz = (uint32_t)(kvRow & 7);
#pragma unroll
            for (int ntp = 0; ntp < 8; ntp++) {
                const int d0 = ntp * 16;
                const uint32_t sub = (d0 >= 64) ? 16384u : 0u;
                const int c8 = ((d0 & 63) + dSel) >> 3;
                uint32_t bd = rowBase + sub + (uint32_t)(((uint32_t)c8 ^ swz) * 16);
                uint32_t bv[4];
                ldmx4t(bv, bd);
                mma16816(o[ntp * 2],     ap, bv);
                mma16816(o[ntp * 2 + 1], ap, bv + 2);
            }
        }
    }

    const float inv0 = 1.0f / lrow[0];
    const float inv1 = 1.0f / lrow[1];
    const long long row0 = (long long)b * SS + qt * 128 + wrow + (lane >> 2);
#pragma unroll
    for (int nt = 0; nt < 16; nt++) {
        int dcol = h * DHH + nt * 8 + 2 * (lane & 3);
        uint32_t h0 = packh2(o[nt][0] * inv0, o[nt][1] * inv0);
        uint32_t h1 = packh2(o[nt][2] * inv1, o[nt][3] * inv1);
        *reinterpret_cast<uint32_t*>(&og[row0 * DD + dcol]) = h0;
        *reinterpret_cast<uint32_t*>(&og[(row0 + 8) * DD + dcol]) = h1;
    }
}

// ------------------------- elementwise kernels --------------------------------
__global__ __launch_bounds__(256)
void rmsnorm_h16(const float* __restrict__ in, const float* __restrict__ w,
                 h16* __restrict__ o)
{
    __shared__ float red[256];
    const long long row = blockIdx.x;
    const float4* p = reinterpret_cast<const float4*>(in + row * DD);
    const float4* wp = reinterpret_cast<const float4*>(w);
    const int tid = threadIdx.x;
    float4 v[2];
    v[0] = p[tid];
    v[1] = p[tid + 256];
    float ss = v[0].x * v[0].x + v[0].y * v[0].y + v[0].z * v[0].z + v[0].w * v[0].w
             + v[1].x * v[1].x + v[1].y * v[1].y + v[1].z * v[1].z + v[1].w * v[1].w;
    red[tid] = ss;
    __syncthreads();
    for (int s = 128; s > 0; s >>= 1) {
        if (tid < s) red[tid] += red[tid + s];
        __syncthreads();
    }
    const float scale = rsqrtf(red[0] / (float)DD + 1e-6f);
    uint32_t* op = reinterpret_cast<uint32_t*>(o + row * DD);
#pragma unroll
    for (int t = 0; t < 2; t++) {
        const int j4 = tid + t * 256;
        const float4 ww = wp[j4];
        op[j4 * 2]     = packh2(v[t].x * scale * ww.x, v[t].y * scale * ww.y);
        op[j4 * 2 + 1] = packh2(v[t].z * scale * ww.z, v[t].w * scale * ww.w);
    }
}

// W [K,N] fp32 -> WT row (n*rowMul + rowOff) of [*, K] fp16
__global__ __launch_bounds__(256)
void transpose_h16(const float* __restrict__ W, h16* __restrict__ out, int K, int N,
                   int rowMul, int rowOff)
{
    __shared__ float t[32][33];
    const int k0 = blockIdx.y * 32, n0 = blockIdx.x * 32;
    const int tx = threadIdx.x & 31, ty = threadIdx.x >> 5;
#pragma unroll
    for (int i = 0; i < 32; i += 8)
        t[ty + i][tx] = W[(long long)(k0 + ty + i) * N + n0 + tx];
    __syncthreads();
#pragma unroll
    for (int i = 0; i < 32; i += 8)
        out[(long long)((n0 + ty + i) * rowMul + rowOff) * K + k0 + tx] =
            __float2half_rn(t[tx][ty + i]);
}

// ------------------------- host ----------------------------------------------
#define GEMM_SMEM (3 * 32768)

static void gemm(const h16* A, const h16* B, const float* Res, float* C,
                 h16* C16, h16* O2, h16* O3, const float* FC, const float* FS,
                 int M, int N, int K,
                 long long lda, long long ldb, long long ldc, long long ldres,
                 float alpha, int mode, cudaStream_t st)
{
    dim3 grid(N / 128, M / 128, 1);
    hgemm<<<grid, 256, GEMM_SMEM, st>>>(A, B, Res, C, C16, O2, O3, FC, FS,
                                        M, N, K, lda, ldb, ldc, ldres, alpha, mode);
}

extern "C" void kernel_launch(void* const* d_in, const int* in_sizes, int n_in,
                              void* d_out, int out_size)
{
    (void)in_sizes; (void)n_in; (void)out_size;
    const float* hidden = (const float*)d_in[0];
    const float* fcos   = (const float*)d_in[1];
    const float* fsin   = (const float*)d_in[2];
    const float* wq     = (const float*)d_in[3];
    const float* wk     = (const float*)d_in[4];
    const float* wv     = (const float*)d_in[5];
    const float* wo     = (const float*)d_in[6];
    const float* w1     = (const float*)d_in[7];
    const float* w2     = (const float*)d_in[8];
    const float* w3     = (const float*)d_in[9];
    const float* anw    = (const float*)d_in[10];
    const float* fnw    = (const float*)d_in[11];
    float* out = (float*)d_out;

    static cudaStream_t s2 = nullptr;
    static cudaEvent_t evF = nullptr, evA = nullptr, evW = nullptr, evB = nullptr;
    if (s2 == nullptr) {
        cudaStreamCreateWithFlags(&s2, cudaStreamNonBlocking);
        cudaEventCreateWithFlags(&evF, cudaEventDisableTiming);
        cudaEventCreateWithFlags(&evA, cudaEventDisableTiming);
        cudaEventCreateWithFlags(&evW, cudaEventDisableTiming);
        cudaEventCreateWithFlags(&evB, cudaEventDisableTiming);
    }

    cudaFuncSetAttribute(hgemm, cudaFuncAttributeMaxDynamicSharedMemorySize, GEMM_SMEM);
    cudaFuncSetAttribute(flash_attn, cudaFuncAttributeMaxDynamicSharedMemorySize, FA_SMEM);

    h16 *xb, *wqkvT, *woT, *w13T, *w2T, *qb, *kb, *vb, *attnb, *yb, *gb;
    float *h;
    cudaGetSymbolAddress((void**)&xb,    g_xb);
    cudaGetSymbolAddress((void**)&wqkvT, g_wqkvT);
    cudaGetSymbolAddress((void**)&woT,   g_woT);
    cudaGetSymbolAddress((void**)&w13T,  g_w13T);
    cudaGetSymbolAddress((void**)&w2T,   g_w2T);
    cudaGetSymbolAddress((void**)&qb,    g_qb);
    cudaGetSymbolAddress((void**)&kb,    g_kb);
    cudaGetSymbolAddress((void**)&vb,    g_vb);
    cudaGetSymbolAddress((void**)&attnb, g_attnb);
    cudaGetSymbolAddress((void**)&h,     g_h);
    cudaGetSymbolAddress((void**)&yb,    g_yb);
    cudaGetSymbolAddress((void**)&gb,    g_gb);

    // ---- fork side stream: QKV weight prep (as in R13)
    cudaEventRecord(evF, 0);
    cudaStreamWaitEvent(s2, evF, 0);
    { dim3 g(DD / 32, DD / 32);
      transpose_h16<<<g, 256, 0, s2>>>(wq, wqkvT,                          DD, DD, 1, 0);
      transpose_h16<<<g, 256, 0, s2>>>(wk, wqkvT + (long long)DD * DD,     DD, DD, 1, 0);
      transpose_h16<<<g, 256, 0, s2>>>(wv, wqkvT + (long long)2 * DD * DD, DD, DD, 1, 0); }
    cudaEventRecord(evA, s2);

    // ---- main chain
    rmsnorm_h16<<<MM, 256>>>(hidden, anw, xb);

    cudaStreamWaitEvent(0, evA, 0);
    // qkv GEMM with fused rope epilogue -> qb (roped+scaled), kb (roped), vb
    gemm(xb, wqkvT, nullptr, nullptr, qb, kb, vb, fcos, fsin,
         MM, QKVN, DD, DD, DD, DD, 0, 1.0f, 3, 0);

    // fused flash attention (LPT grid, peeled diagonal) -> attnb fp16
    flash_attn<<<(SS / 128) * BBATCH * HH, 256, FA_SMEM>>>(qb, kb, vb, attnb);

    // ---- remaining weight prep on s2 (overlaps qkv/attention)
    { dim3 g(DD / 32, DD / 32);
      transpose_h16<<<g, 256, 0, s2>>>(wo, woT, DD, DD, 1, 0); }
    cudaEventRecord(evW, s2);
    { dim3 g(FFD / 32, DD / 32);
      transpose_h16<<<g, 256, 0, s2>>>(w1, w13T, DD, FFD, 2, 0);   // even rows
      transpose_h16<<<g, 256, 0, s2>>>(w3, w13T, DD, FFD, 2, 1); } // odd rows
    { dim3 g(DD / 32, FFD / 32);
      transpose_h16<<<g, 256, 0, s2>>>(w2, w2T, FFD, DD, 1, 0); }
    cudaEventRecord(evB, s2);

    cudaStreamWaitEvent(0, evW, 0);
    // h = hidden + attn @ wo
    gemm(attnb, woT, hidden, h, nullptr, nullptr, nullptr, nullptr, nullptr,
         MM, DD, DD, DD, DD, DD, DD, 1.0f, 0, 0);

    // y = rmsnorm(h) -> fp16
    rmsnorm_h16<<<MM, 256>>>(h, fnw, yb);

    cudaStreamWaitEvent(0, evB, 0);
    // g = silu(y@w1) * (y@w3) -> fp16 (fused epilogue, interleaved weights)
    gemm(yb, w13T, nullptr, nullptr, gb, nullptr, nullptr, nullptr, nullptr,
         MM, F13N, DD, DD, DD, FFD, 0, 1.0f, 2, 0);

    // out = h + g @ w2
    gemm(gb, w2T, h, out, nullptr, nullptr, nullptr, nullptr, nullptr,
         MM, DD, FFD, FFD, FFD, DD, DD, 1.0f, 0, 0);
}

// round 16
// speedup vs baseline: 1.0199x; 1.0149x over previous
#include <cuda_runtime.h>
#include <cuda_fp16.h>
#include <math.h>
#include <stdint.h>

#define BBATCH 2
#define SS 2048
#define DD 2048
#define HH 16
#define DHH 128
#define FFD 5632
#define MM (BBATCH * SS)
#define QKVN (3 * DD)        // 6144
#define F13N (2 * FFD)       // 11264

typedef __half h16;

// ------------------------- scratch (device globals) -------------------------
__device__ h16   g_xb   [(long long)MM * DD];
__device__ h16   g_wqkvT[(long long)QKVN * DD];
__device__ h16   g_woT  [(long long)DD * DD];
__device__ h16   g_w13T [(long long)F13N * DD];   // interleaved: row 2j = w1_j, 2j+1 = w3_j
__device__ h16   g_w2T  [(long long)DD * FFD];
__device__ h16   g_qb   [(long long)MM * DD];
__device__ h16   g_kb   [(long long)MM * DD];
__device__ h16   g_vb   [(long long)MM * DD];
__device__ h16   g_attnb[(long long)MM * DD];
__device__ h16   g_hb   [(long long)MM * DD];     // attention-residual stream, fp16
__device__ h16   g_yb   [(long long)MM * DD];
__device__ h16   g_gb   [(long long)MM * FFD];

// ------------------------- helpers ------------------------------------------
__device__ __forceinline__ uint32_t smem_u32(const void* p) {
    uint32_t a;
    asm("{ .reg .u64 t; cvta.to.shared.u64 t, %1; cvt.u32.u64 %0, t; }" : "=r"(a) : "l"(p));
    return a;
}

__device__ __forceinline__ void cp_async16(uint32_t dst, const void* src) {
    asm volatile("cp.async.cg.shared.global [%0], [%1], 16;" :: "r"(dst), "l"(src));
}
__device__ __forceinline__ void cp_commit() {
    asm volatile("cp.async.commit_group;");
}
__device__ __forceinline__ void cp_wait1() {
    asm volatile("cp.async.wait_group 1;");
}
__device__ __forceinline__ void cp_wait0() {
    asm volatile("cp.async.wait_group 0;");
}

__device__ __forceinline__ void ldmx4(uint32_t* r, uint32_t addr) {
    asm volatile("ldmatrix.sync.aligned.m8n8.x4.shared.b16 {%0,%1,%2,%3}, [%4];"
                 : "=r"(r[0]), "=r"(r[1]), "=r"(r[2]), "=r"(r[3]) : "r"(addr));
}
__device__ __forceinline__ void ldmx4t(uint32_t* r, uint32_t addr) {
    asm volatile("ldmatrix.sync.aligned.m8n8.x4.trans.shared.b16 {%0,%1,%2,%3}, [%4];"
                 : "=r"(r[0]), "=r"(r[1]), "=r"(r[2]), "=r"(r[3]) : "r"(addr));
}
__device__ __forceinline__ void mma16816(float* c, const uint32_t* a, const uint32_t* b) {
    asm volatile(
        "mma.sync.aligned.m16n8k16.row.col.f32.f16.f16.f32 "
        "{%0,%1,%2,%3}, {%4,%5,%6,%7}, {%8,%9}, {%0,%1,%2,%3};"
        : "+f"(c[0]), "+f"(c[1]), "+f"(c[2]), "+f"(c[3])
        : "r"(a[0]), "r"(a[1]), "r"(a[2]), "r"(a[3]), "r"(b[0]), "r"(b[1]));
}
__device__ __forceinline__ uint32_t packh2(float a, float b) {
    __half2 h = __floats2half2_rn(a, b);
    return *reinterpret_cast<uint32_t*>(&h);
}
__device__ __forceinline__ float siluf(float a) {
    return a / (1.0f + __expf(-a));
}

// ------------------------- HGEMM (mma.sync) ----------------------------------
// C[m][n] = sum_k A[m][k]*B[n][k] (+Res).  A/B K-major fp16.
// mode 0: fp32 out, residual from Res16 (h16) if nonnull else Res (fp32)
// mode 2: silu-pair fp16 out; mode 3: QKV rope epilogue
// mode 4: fp16 out with fp32 residual (wo GEMM -> h stream)
__device__ __forceinline__ void stage_load(uint32_t sdst, const h16* g, int row0,
                                           long long ld, int k0, int tid)
{
    const int r = tid >> 1;
    const int cb = (tid & 1) * 4;
    const h16* grow = g + (long long)(row0 + r) * ld + k0;
#pragma unroll
    for (int i = 0; i < 4; i++) {
        int c = cb + i;
        uint32_t dst = sdst + (uint32_t)(r * 128 + ((c ^ (r & 7)) * 16));
        cp_async16(dst, grow + c * 8);
    }
}

#define SM_SCALE 0.08838834764831845f

__global__ __launch_bounds__(256, 2)
void hgemm(const h16* __restrict__ A, const h16* __restrict__ B,
           const float* __restrict__ Res, const h16* __restrict__ Res16,
           float* __restrict__ C,
           h16* __restrict__ C16, h16* __restrict__ O2, h16* __restrict__ O3,
           const float* __restrict__ FC, const float* __restrict__ FS,
           int M, int N, int K,
           long long lda, long long ldb, long long ldc, long long ldres,
           int mode)
{
    extern __shared__ char smem[];

    const int m0 = blockIdx.y * 128;
    const int n0 = blockIdx.x * 128;

    const int tid = threadIdx.x;
    const int lane = tid & 31;
    const int wid = tid >> 5;
    const int wm = wid >> 2;
    const int wn = wid & 3;

    const uint32_t sb = smem_u32(smem);
    const int KT = K >> 6;

    const int nPro = (KT < 2) ? KT : 2;
    for (int s = 0; s < nPro; s++) {
        uint32_t base = sb + (uint32_t)(s % 3) * 32768u;
        stage_load(base, A, m0, lda, s * 64, tid);
        stage_load(base + 16384u, B, n0, ldb, s * 64, tid);
        cp_commit();
    }

    float acc[4][4][4];
#pragma unroll
    for (int i = 0; i < 4; i++)
#pragma unroll
        for (int j = 0; j < 4; j++)
#pragma unroll
            for (int q = 0; q < 4; q++) acc[i][j][q] = 0.0f;

    const int aRow = wm * 64 + (lane & 15);
    const int aKsel = lane >> 4;
    const int aSwz = aRow & 7;
    const int bRow7 = lane & 7;
    const int bKsel = (lane >> 3) & 1;
    const int bNtSel = (lane >> 4) & 1;

    for (int s = 0; s < KT; s++) {
        cp_wait1();
        __syncthreads();            // single barrier per stage
        if (s + 2 < KT) {
            uint32_t base = sb + (uint32_t)((s + 2) % 3) * 32768u;
            stage_load(base, A, m0, lda, (s + 2) * 64, tid);
            stage_load(base + 16384u, B, n0, ldb, (s + 2) * 64, tid);
        }
        cp_commit();

        const uint32_t base = sb + (uint32_t)(s % 3) * 32768u;
#pragma unroll
        for (int kc = 0; kc < 4; kc++) {
            uint32_t a[4][4], b[2][4];
#pragma unroll
            for (int mt = 0; mt < 4; mt++) {
                uint32_t ad = base + (uint32_t)((aRow + mt * 16) * 128 +
                              (((kc * 2 + aKsel) ^ aSwz) * 16));
                ldmx4(a[mt], ad);
            }
#pragma unroll
            for (int ntp = 0; ntp < 2; ntp++) {
                int nRow = wn * 32 + (ntp * 2 + bNtSel) * 8 + bRow7;
                uint32_t bd = base + 16384u + (uint32_t)(nRow * 128 +
                              (((kc * 2 + bKsel) ^ (nRow & 7)) * 16));
                ldmx4(b[ntp], bd);
            }
#pragma unroll
            for (int mt = 0; mt < 4; mt++) {
                mma16816(acc[mt][0], a[mt], b[0]);
                mma16816(acc[mt][1], a[mt], b[0] + 2);
                mma16816(acc[mt][2], a[mt], b[1]);
                mma16816(acc[mt][3], a[mt], b[1] + 2);
            }
        }
    }
    __syncthreads();

#pragma unroll
    for (int mt = 0; mt < 4; mt++) {
#pragma unroll
        for (int nt = 0; nt < 4; nt++) {
            const int m = m0 + wm * 64 + mt * 16 + (lane >> 2);
            const int n = n0 + wn * 32 + nt * 8 + (lane & 3) * 2;
            if (mode == 3) {
                const int i = (n & 127) >> 1;
                if (n < 2 * DD) {
                    const bool isQ = (n < DD);
                    h16* dst = isQ ? C16 : O2;
                    const float sc = isQ ? SM_SCALE : 1.0f;
                    const int ncol = n & (DD - 1);
                    const int s1 = m & (SS - 1);
                    const int s2 = (m + 8) & (SS - 1);
                    const float c1 = FC[s1 * 64 + i], sn1 = FS[s1 * 64 + i];
                    const float c2 = FC[s2 * 64 + i], sn2 = FS[s2 * 64 + i];
                    uint32_t h0 = packh2((acc[mt][nt][0] * c1 - acc[mt][nt][1] * sn1) * sc,
                                         (acc[mt][nt][0] * sn1 + acc[mt][nt][1] * c1) * sc);
                    uint32_t h1 = packh2((acc[mt][nt][2] * c2 - acc[mt][nt][3] * sn2) * sc,
                                         (acc[mt][nt][2] * sn2 + acc[mt][nt][3] * c2) * sc);
                    *reinterpret_cast<uint32_t*>(&dst[(long long)m * DD + ncol]) = h0;
                    *reinterpret_cast<uint32_t*>(&dst[(long long)(m + 8) * DD + ncol]) = h1;
                } else {
                    const int ncol = n - 2 * DD;
                    uint32_t h0 = packh2(acc[mt][nt][0], acc[mt][nt][1]);
                    uint32_t h1 = packh2(acc[mt][nt][2], acc[mt][nt][3]);
                    *reinterpret_cast<uint32_t*>(&O3[(long long)m * DD + ncol]) = h0;
                    *reinterpret_cast<uint32_t*>(&O3[(long long)(m + 8) * DD + ncol]) = h1;
                }
            } else if (mode == 2) {
                const int j = n >> 1;
                float g0 = siluf(acc[mt][nt][0]) * acc[mt][nt][1];
                float g1 = siluf(acc[mt][nt][2]) * acc[mt][nt][3];
                float g0p = __shfl_xor_sync(0xffffffffu, g0, 1);
                float g1p = __shfl_xor_sync(0xffffffffu, g1, 1);
                if (!(lane & 1)) {
                    *reinterpret_cast<uint32_t*>(&C16[(long long)m * ldc + j]) = packh2(g0, g0p);
                    *reinterpret_cast<uint32_t*>(&C16[(long long)(m + 8) * ldc + j]) = packh2(g1, g1p);
                }
            } else if (mode == 4) {
                // fp16 out + fp32 residual (wo GEMM -> h stream)
                float2 r0 = *reinterpret_cast<const float2*>(&Res[(long long)m * ldres + n]);
                float2 r1 = *reinterpret_cast<const float2*>(&Res[(long long)(m + 8) * ldres + n]);
                *reinterpret_cast<uint32_t*>(&C16[(long long)m * ldc + n]) =
                    packh2(acc[mt][nt][0] + r0.x, acc[mt][nt][1] + r0.y);
                *reinterpret_cast<uint32_t*>(&C16[(long long)(m + 8) * ldc + n]) =
                    packh2(acc[mt][nt][2] + r1.x, acc[mt][nt][3] + r1.y);
            } else {
                float2 v0, v1;
                v0.x = acc[mt][nt][0]; v0.y = acc[mt][nt][1];
                v1.x = acc[mt][nt][2]; v1.y = acc[mt][nt][3];
                if (Res16) {
                    __half2 hr0 = *reinterpret_cast<const __half2*>(&Res16[(long long)m * ldres + n]);
                    __half2 hr1 = *reinterpret_cast<const __half2*>(&Res16[(long long)(m + 8) * ldres + n]);
                    float2 r0 = __half22float2(hr0);
                    float2 r1 = __half22float2(hr1);
                    v0.x += r0.x; v0.y += r0.y; v1.x += r1.x; v1.y += r1.y;
                } else if (Res) {
                    float2 r0 = *reinterpret_cast<const float2*>(&Res[(long long)m * ldres + n]);
                    float2 r1 = *reinterpret_cast<const float2*>(&Res[(long long)(m + 8) * ldres + n]);
                    v0.x += r0.x; v0.y += r0.y; v1.x += r1.x; v1.y += r1.y;
                }
                *reinterpret_cast<float2*>(&C[(long long)m * ldc + n]) = v0;
                *reinterpret_cast<float2*>(&C[(long long)(m + 8) * ldc + n]) = v1;
            }
        }
    }
}

// ------------------------- fused flash attention ------------------------------
// 1-D grid of 512 (LPT). Mainloop kt in [0,qt) is branch-free; diagonal tile
// peeled into a separate section with wid-bounded loops (skipped work is zero).
#define FA_SMEM (32768 + 2 * 65536)

__global__ __launch_bounds__(256, 1)
void flash_attn(const h16* __restrict__ qg, const h16* __restrict__ kg,
                const h16* __restrict__ vg, h16* __restrict__ og)
{
    extern __shared__ char smem[];
    const int NQT = SS / 128;                     // 16
    const int idx = blockIdx.x;
    const int qt = (NQT - 1) - (idx >> 5);        // heavy first, 32 bh per qt band
    const int bh = idx & 31;
    const int b = bh >> 4, h = bh & 15;

    const h16* qp = qg + (long long)b * SS * DD + h * DHH;
    const h16* kp = kg + (long long)b * SS * DD + h * DHH;
    const h16* vp = vg + (long long)b * SS * DD + h * DHH;

    const int tid = threadIdx.x;
    const int lane = tid & 31;
    const int wid = tid >> 5;
    const int wrow = wid * 16;

    const uint32_t sb = smem_u32(smem);
    const uint32_t qbs = sb;

    stage_load(qbs, qp, qt * 128, DD, 0, tid);
    stage_load(qbs + 16384u, qp, qt * 128, DD, 64, tid);
    cp_commit();
    {
        uint32_t kvb = sb + 32768u;
        stage_load(kvb, kp, 0, DD, 0, tid);
        stage_load(kvb + 16384u, kp, 0, DD, 64, tid);
        stage_load(kvb + 32768u, vp, 0, DD, 0, tid);
        stage_load(kvb + 49152u, vp, 0, DD, 64, tid);
        cp_commit();
    }

    const int aRow = wrow + (lane & 15);
    const int aKsel = lane >> 4;
    const int aSwz = aRow & 7;
    const int bRow7 = lane & 7;
    const int bNtSel = (lane >> 4) & 1;
    const int bKsel = (lane >> 3) & 1;
    const int kvRowBase = (lane & 7) + ((lane >> 3) & 1) * 8;
    const int dSel = (lane >> 4) ? 8 : 0;

    uint32_t aq[8][4];
    float o[16][4];
    float mrow[2], lrow[2];
#pragma unroll
    for (int i = 0; i < 16; i++)
#pragma unroll
        for (int j = 0; j < 4; j++) o[i][j] = 0.0f;
    mrow[0] = mrow[1] = -1e30f;
    lrow[0] = lrow[1] = 0.0f;

    // ---- mainloop: off-diagonal tiles, fully unrolled bodies, no masking
    for (int kt = 0; kt < qt; kt++) {
        cp_wait0();
        __syncthreads();
        const uint32_t kvb = sb + 32768u + (uint32_t)(kt & 1) * 65536u;
        {
            uint32_t nb = sb + 32768u + (uint32_t)((kt + 1) & 1) * 65536u;
            stage_load(nb, kp, (kt + 1) * 128, DD, 0, tid);
            stage_load(nb + 16384u, kp, (kt + 1) * 128, DD, 64, tid);
            stage_load(nb + 32768u, vp, (kt + 1) * 128, DD, 0, tid);
            stage_load(nb + 49152u, vp, (kt + 1) * 128, DD, 64, tid);
            cp_commit();
        }
        if (kt == 0) {
#pragma unroll
            for (int kc = 0; kc < 8; kc++) {
                uint32_t base = qbs + (kc >= 4 ? 16384u : 0u);
                uint32_t ad = base + (uint32_t)(aRow * 128 +
                              ((((kc & 3) * 2 + aKsel) ^ aSwz) * 16));
                ldmx4(aq[kc], ad);
            }
        }

        float s[16][4];
#pragma unroll
        for (int i = 0; i < 16; i++)
#pragma unroll
            for (int j = 0; j < 4; j++) s[i][j] = 0.0f;
#pragma unroll
        for (int ntp = 0; ntp < 8; ntp++) {
#pragma unroll
            for (int kc = 0; kc < 8; kc++) {
                uint32_t base = kvb + (kc >= 4 ? 16384u : 0u);
                int nRow = (ntp * 2 + bNtSel) * 8 + bRow7;
                uint32_t bd = base + (uint32_t)(nRow * 128 +
                              ((((kc & 3) * 2 + bKsel) ^ (nRow & 7)) * 16));
                uint32_t bv[4];
                ldmx4(bv, bd);
                mma16816(s[ntp * 2],     aq[kc], bv);
                mma16816(s[ntp * 2 + 1], aq[kc], bv + 2);
            }
        }

        float mx0 = -1e30f, mx1 = -1e30f;
#pragma unroll
        for (int nt = 0; nt < 16; nt++) {
            mx0 = fmaxf(mx0, fmaxf(s[nt][0], s[nt][1]));
            mx1 = fmaxf(mx1, fmaxf(s[nt][2], s[nt][3]));
        }
        mx0 = fmaxf(mx0, __shfl_xor_sync(0xffffffffu, mx0, 1));
        mx0 = fmaxf(mx0, __shfl_xor_sync(0xffffffffu, mx0, 2));
        mx1 = fmaxf(mx1, __shfl_xor_sync(0xffffffffu, mx1, 1));
        mx1 = fmaxf(mx1, __shfl_xor_sync(0xffffffffu, mx1, 2));
        const float mn0 = fmaxf(mrow[0], mx0);
        const float mn1 = fmaxf(mrow[1], mx1);
        const float f0 = __expf(mrow[0] - mn0);
        const float f1 = __expf(mrow[1] - mn1);
        mrow[0] = mn0; mrow[1] = mn1;
#pragma unroll
        for (int nt = 0; nt < 16; nt++) {
            o[nt][0] *= f0; o[nt][1] *= f0;
            o[nt][2] *= f1; o[nt][3] *= f1;
        }
        float sum0 = 0.0f, sum1 = 0.0f;
#pragma unroll
        for (int nt = 0; nt < 16; nt++) {
            s[nt][0] = __expf(s[nt][0] - mn0);
            s[nt][1] = __expf(s[nt][1] - mn0);
            s[nt][2] = __expf(s[nt][2] - mn1);
            s[nt][3] = __expf(s[nt][3] - mn1);
            sum0 += s[nt][0] + s[nt][1];
            sum1 += s[nt][2] + s[nt][3];
        }
        sum0 += __shfl_xor_sync(0xffffffffu, sum0, 1);
        sum0 += __shfl_xor_sync(0xffffffffu, sum0, 2);
        sum1 += __shfl_xor_sync(0xffffffffu, sum1, 1);
        sum1 += __shfl_xor_sync(0xffffffffu, sum1, 2);
        lrow[0] = lrow[0] * f0 + sum0;
        lrow[1] = lrow[1] * f1 + sum1;

#pragma unroll
        for (int kc = 0; kc < 8; kc++) {
            uint32_t ap[4];
            ap[0] = packh2(s[kc * 2][0], s[kc * 2][1]);
            ap[1] = packh2(s[kc * 2][2], s[kc * 2][3]);
            ap[2] = packh2(s[kc * 2 + 1][0], s[kc * 2 + 1][1]);
            ap[3] = packh2(s[kc * 2 + 1][2], s[kc * 2 + 1][3]);
            const int kvRow = kc * 16 + kvRowBase;
            const uint32_t rowBase = kvb + 32768u + (uint32_t)(kvRow * 128);
            const uint32_t swz = (uint32_t)(kvRow & 7);
#pragma unroll
            for (int ntp = 0; ntp < 8; ntp++) {
                const int d0 = ntp * 16;
                const uint32_t sub = (d0 >= 64) ? 16384u : 0u;
                const int c8 = ((d0 & 63) + dSel) >> 3;
                uint32_t bd = rowBase + sub + (uint32_t)(((uint32_t)c8 ^ swz) * 16);
                uint32_t bv[4];
                ldmx4t(bv, bd);
                mma16816(o[ntp * 2],     ap, bv);
                mma16816(o[ntp * 2 + 1], ap, bv + 2);
            }
        }
    }

    // ---- peeled diagonal tile (kt == qt): wid-bounded loops
    {
        cp_wait0();
        __syncthreads();
        const uint32_t kvb = sb + 32768u + (uint32_t)(qt & 1) * 65536u;
        if (qt == 0) {
#pragma unroll
            for (int kc = 0; kc < 8; kc++) {
                uint32_t base = qbs + (kc >= 4 ? 16384u : 0u);
                uint32_t ad = base + (uint32_t)(aRow * 128 +
                              ((((kc & 3) * 2 + aKsel) ^ aSwz) * 16));
                ldmx4(aq[kc], ad);
            }
        }

        float s[16][4];
#pragma unroll
        for (int i = 0; i < 16; i++)
#pragma unroll
            for (int j = 0; j < 4; j++) s[i][j] = 0.0f;
        for (int ntp = 0; ntp <= wid; ntp++) {      // chunks beyond wid fully masked
#pragma unroll
            for (int kc = 0; kc < 8; kc++) {
                uint32_t base = kvb + (kc >= 4 ? 16384u : 0u);
                int nRow = (ntp * 2 + bNtSel) * 8 + bRow7;
                uint32_t bd = base + (uint32_t)(nRow * 128 +
                              ((((kc & 3) * 2 + bKsel) ^ (nRow & 7)) * 16));
                uint32_t bv[4];
                ldmx4(bv, bd);
                mma16816(s[ntp * 2],     aq[kc], bv);
                mma16816(s[ntp * 2 + 1], aq[kc], bv + 2);
            }
        }

        {
            const int ii0 = wrow + (lane >> 2);
#pragma unroll
            for (int nt = 0; nt < 16; nt++) {
                int jj = nt * 8 + 2 * (lane & 3);
                if (jj > ii0)      s[nt][0] = -1e30f;
                if (jj + 1 > ii0)  s[nt][1] = -1e30f;
                if (jj > ii0 + 8)     s[nt][2] = -1e30f;
                if (jj + 1 > ii0 + 8) s[nt][3] = -1e30f;
            }
        }

        float mx0 = -1e30f, mx1 = -1e30f;
#pragma unroll
        for (int nt = 0; nt < 16; nt++) {
            mx0 = fmaxf(mx0, fmaxf(s[nt][0], s[nt][1]));
            mx1 = fmaxf(mx1, fmaxf(s[nt][2], s[nt][3]));
        }
        mx0 = fmaxf(mx0, __shfl_xor_sync(0xffffffffu, mx0, 1));
        mx0 = fmaxf(mx0, __shfl_xor_sync(0xffffffffu, mx0, 2));
        mx1 = fmaxf(mx1, __shfl_xor_sync(0xffffffffu, mx1, 1));
        mx1 = fmaxf(mx1, __shfl_xor_sync(0xffffffffu, mx1, 2));
        const float mn0 = fmaxf(mrow[0], mx0);
        const float mn1 = fmaxf(mrow[1], mx1);
        const float f0 = __expf(mrow[0] - mn0);
        const float f1 = __expf(mrow[1] - mn1);
        mrow[0] = mn0; mrow[1] = mn1;
#pragma unroll
        for (int nt = 0; nt < 16; nt++) {
            o[nt][0] *= f0; o[nt][1] *= f0;
            o[nt][2] *= f1; o[nt][3] *= f1;
        }
        float sum0 = 0.0f, sum1 = 0.0f;
#pragma unroll
        for (int nt = 0; nt < 16; nt++) {
            s[nt][0] = __expf(s[nt][0] - mn0);
            s[nt][1] = __expf(s[nt][1] - mn0);
            s[nt][2] = __expf(s[nt][2] - mn1);
            s[nt][3] = __expf(s[nt][3] - mn1);
            sum0 += s[nt][0] + s[nt][1];
            sum1 += s[nt][2] + s[nt][3];
        }
        sum0 += __shfl_xor_sync(0xffffffffu, sum0, 1);
        sum0 += __shfl_xor_sync(0xffffffffu, sum0, 2);
        sum1 += __shfl_xor_sync(0xffffffffu, sum1, 1);
        sum1 += __shfl_xor_sync(0xffffffffu, sum1, 2);
        lrow[0] = lrow[0] * f0 + sum0;
        lrow[1] = lrow[1] * f1 + sum1;

        for (int kc = 0; kc <= wid; kc++) {         // P beyond wid is exactly 0
            uint32_t ap[4];
            ap[0] = packh2(s[kc * 2][0], s[kc * 2][1]);
            ap[1] = packh2(s[kc * 2][2], s[kc * 2][3]);
            ap[2] = packh2(s[kc * 2 + 1][0], s[kc * 2 + 1][1]);
            ap[3] = packh2(s[kc * 2 + 1][2], s[kc * 2 + 1][3]);
            const int kvRow = kc * 16 + kvRowBase;
            const uint32_t rowBase = kvb + 32768u + (uint32_t)(kvRow * 128);
            const uint32_t swz = (uint32_t)(kvRow & 7);
#pragma unroll
            for (int ntp = 0; ntp < 8; ntp++) {
                const int d0 = ntp * 16;
                const uint32_t sub = (d0 >= 64) ? 16384u : 0u;
                const int c8 = ((d0 & 63) + dSel) >> 3;
                uint32_t bd = rowBase + sub + (uint32_t)(((uint32_t)c8 ^ swz) * 16);
                uint32_t bv[4];
                ldmx4t(bv, bd);
                mma16816(o[ntp * 2],     ap, bv);
                mma16816(o[ntp * 2 + 1], ap, bv + 2);
            }
        }
    }

    const float inv0 = 1.0f / lrow[0];
    const float inv1 = 1.0f / lrow[1];
    const long long row0 = (long long)b * SS + qt * 128 + wrow + (lane >> 2);
#pragma unroll
    for (int nt = 0; nt < 16; nt++) {
        int dcol = h * DHH + nt * 8 + 2 * (lane & 3);
        uint32_t h0 = packh2(o[nt][0] * inv0, o[nt][1] * inv0);
        uint32_t h1 = packh2(o[nt][2] * inv1, o[nt][3] * inv1);
        *reinterpret_cast<uint32_t*>(&og[row0 * DD + dcol]) = h0;
        *reinterpret_cast<uint32_t*>(&og[(row0 + 8) * DD + dcol]) = h1;
    }
}

// ------------------------- elementwise kernels --------------------------------
__global__ __launch_bounds__(256)
void rmsnorm_h16(const float* __restrict__ in, const float* __restrict__ w,
                 h16* __restrict__ o)
{
    __shared__ float red[256];
    const long long row = blockIdx.x;
    const float4* p = reinterpret_cast<const float4*>(in + row * DD);
    const float4* wp = reinterpret_cast<const float4*>(w);
    const int tid = threadIdx.x;
    float4 v[2];
    v[0] = p[tid];
    v[1] = p[tid + 256];
    float ss = v[0].x * v[0].x + v[0].y * v[0].y + v[0].z * v[0].z + v[0].w * v[0].w
             + v[1].x * v[1].x + v[1].y * v[1].y + v[1].z * v[1].z + v[1].w * v[1].w;
    red[tid] = ss;
    __syncthreads();
    for (int s = 128; s > 0; s >>= 1) {
        if (tid < s) red[tid] += red[tid + s];
        __syncthreads();
    }
    const float scale = rsqrtf(red[0] / (float)DD + 1e-6f);
    uint32_t* op = reinterpret_cast<uint32_t*>(o + row * DD);
#pragma unroll
    for (int t = 0; t < 2; t++) {
        const int j4 = tid + t * 256;
        const float4 ww = wp[j4];
        op[j4 * 2]     = packh2(v[t].x * scale * ww.x, v[t].y * scale * ww.y);
        op[j4 * 2 + 1] = packh2(v[t].z * scale * ww.z, v[t].w * scale * ww.w);
    }
}

// rmsnorm with fp16 input (h stream)
__global__ __launch_bounds__(256)
void rmsnorm_h16_in16(const h16* __restrict__ in, const float* __restrict__ w,
                      h16* __restrict__ o)
{
    __shared__ float red[256];
    const long long row = blockIdx.x;
    const uint2* p = reinterpret_cast<const uint2*>(in + row * DD);   // 4 halfs each
    const float4* wp = reinterpret_cast<const float4*>(w);
    const int tid = threadIdx.x;
    float4 v[2];
#pragma unroll
    for (int t = 0; t < 2; t++) {
        uint2 raw = p[tid + t * 256];
        float2 lo = __half22float2(*reinterpret_cast<__half2*>(&raw.x));
        float2 hi = __half22float2(*reinterpret_cast<__half2*>(&raw.y));
        v[t].x = lo.x; v[t].y = lo.y; v[t].z = hi.x; v[t].w = hi.y;
    }
    float ss = v[0].x * v[0].x + v[0].y * v[0].y + v[0].z * v[0].z + v[0].w * v[0].w
             + v[1].x * v[1].x + v[1].y * v[1].y + v[1].z * v[1].z + v[1].w * v[1].w;
    red[tid] = ss;
    __syncthreads();
    for (int s = 128; s > 0; s >>= 1) {
        if (tid < s) red[tid] += red[tid + s];
        __syncthreads();
    }
    const float scale = rsqrtf(red[0] / (float)DD + 1e-6f);
    uint32_t* op = reinterpret_cast<uint32_t*>(o + row * DD);
#pragma unroll
    for (int t = 0; t < 2; t++) {
        const int j4 = tid + t * 256;
        const float4 ww = wp[j4];
        op[j4 * 2]     = packh2(v[t].x * scale * ww.x, v[t].y * scale * ww.y);
        op[j4 * 2 + 1] = packh2(v[t].z * scale * ww.z, v[t].w * scale * ww.w);
    }
}

// W [K,N] fp32 -> WT row (n*rowMul + rowOff) of [*, K] fp16
__global__ __launch_bounds__(256)
void transpose_h16(const float* __restrict__ W, h16* __restrict__ out, int K, int N,
                   int rowMul, int rowOff)
{
    __shared__ float t[32][33];
    const int k0 = blockIdx.y * 32, n0 = blockIdx.x * 32;
    const int tx = threadIdx.x & 31, ty = threadIdx.x >> 5;
#pragma unroll
    for (int i = 0; i < 32; i += 8)
        t[ty + i][tx] = W[(long long)(k0 + ty + i) * N + n0 + tx];
    __syncthreads();
#pragma unroll
    for (int i = 0; i < 32; i += 8)
        out[(long long)((n0 + ty + i) * rowMul + rowOff) * K + k0 + tx] =
            __float2half_rn(t[tx][ty + i]);
}

// ------------------------- host ----------------------------------------------
#define GEMM_SMEM (3 * 32768)

static void gemm(const h16* A, const h16* B, const float* Res, const h16* Res16,
                 float* C, h16* C16, h16* O2, h16* O3,
                 const float* FC, const float* FS,
                 int M, int N, int K,
                 long long lda, long long ldb, long long ldc, long long ldres,
                 int mode, cudaStream_t st)
{
    dim3 grid(N / 128, M / 128, 1);
    hgemm<<<grid, 256, GEMM_SMEM, st>>>(A, B, Res, Res16, C, C16, O2, O3, FC, FS,
                                        M, N, K, lda, ldb, ldc, ldres, mode);
}

extern "C" void kernel_launch(void* const* d_in, const int* in_sizes, int n_in,
                              void* d_out, int out_size)
{
    (void)in_sizes; (void)n_in; (void)out_size;
    const float* hidden = (const float*)d_in[0];
    const float* fcos   = (const float*)d_in[1];
    const float* fsin   = (const float*)d_in[2];
    const float* wq     = (const float*)d_in[3];
    const float* wk     = (const float*)d_in[4];
    const float* wv     = (const float*)d_in[5];
    const float* wo     = (const float*)d_in[6];
    const float* w1     = (const float*)d_in[7];
    const float* w2     = (const float*)d_in[8];
    const float* w3     = (const float*)d_in[9];
    const float* anw    = (const float*)d_in[10];
    const float* fnw    = (const float*)d_in[11];
    float* out = (float*)d_out;

    static cudaStream_t s2 = nullptr;
    static cudaEvent_t evF = nullptr, evA = nullptr, evW = nullptr, ev13 = nullptr, evB = nullptr;
    if (s2 == nullptr) {
        cudaStreamCreateWithFlags(&s2, cudaStreamNonBlocking);
        cudaEventCreateWithFlags(&evF, cudaEventDisableTiming);
        cudaEventCreateWithFlags(&evA, cudaEventDisableTiming);
        cudaEventCreateWithFlags(&evW, cudaEventDisableTiming);
        cudaEventCreateWithFlags(&ev13, cudaEventDisableTiming);
        cudaEventCreateWithFlags(&evB, cudaEventDisableTiming);
    }

    cudaFuncSetAttribute(hgemm, cudaFuncAttributeMaxDynamicSharedMemorySize, GEMM_SMEM);
    cudaFuncSetAttribute(flash_attn, cudaFuncAttributeMaxDynamicSharedMemorySize, FA_SMEM);

    h16 *xb, *wqkvT, *woT, *w13T, *w2T, *qb, *kb, *vb, *attnb, *hb, *yb, *gb;
    cudaGetSymbolAddress((void**)&xb,    g_xb);
    cudaGetSymbolAddress((void**)&wqkvT, g_wqkvT);
    cudaGetSymbolAddress((void**)&woT,   g_woT);
    cudaGetSymbolAddress((void**)&w13T,  g_w13T);
    cudaGetSymbolAddress((void**)&w2T,   g_w2T);
    cudaGetSymbolAddress((void**)&qb,    g_qb);
    cudaGetSymbolAddress((void**)&kb,    g_kb);
    cudaGetSymbolAddress((void**)&vb,    g_vb);
    cudaGetSymbolAddress((void**)&attnb, g_attnb);
    cudaGetSymbolAddress((void**)&hb,    g_hb);
    cudaGetSymbolAddress((void**)&yb,    g_yb);
    cudaGetSymbolAddress((void**)&gb,    g_gb);

    // ---- fork side stream: QKV weight prep
    cudaEventRecord(evF, 0);
    cudaStreamWaitEvent(s2, evF, 0);
    { dim3 g(DD / 32, DD / 32);
      transpose_h16<<<g, 256, 0, s2>>>(wq, wqkvT,                          DD, DD, 1, 0);
      transpose_h16<<<g, 256, 0, s2>>>(wk, wqkvT + (long long)DD * DD,     DD, DD, 1, 0);
      transpose_h16<<<g, 256, 0, s2>>>(wv, wqkvT + (long long)2 * DD * DD, DD, DD, 1, 0); }
    cudaEventRecord(evA, s2);

    // ---- main chain
    rmsnorm_h16<<<MM, 256>>>(hidden, anw, xb);

    cudaStreamWaitEvent(0, evA, 0);
    // qkv GEMM with fused rope epilogue -> qb (roped+scaled), kb (roped), vb
    gemm(xb, wqkvT, nullptr, nullptr, nullptr, qb, kb, vb, fcos, fsin,
         MM, QKVN, DD, DD, DD, DD, 0, 3, 0);

    // fused flash attention (LPT grid, peeled diagonal) -> attnb fp16
    flash_attn<<<(SS / 128) * BBATCH * HH, 256, FA_SMEM>>>(qb, kb, vb, attnb);

    // ---- remaining weight prep on s2 (overlaps qkv/attention)
    { dim3 g(DD / 32, DD / 32);
      transpose_h16<<<g, 256, 0, s2>>>(wo, woT, DD, DD, 1, 0); }
    cudaEventRecord(evW, s2);
    { dim3 g(FFD / 32, DD / 32);
      transpose_h16<<<g, 256, 0, s2>>>(w1, w13T, DD, FFD, 2, 0);   // even rows
      transpose_h16<<<g, 256, 0, s2>>>(w3, w13T, DD, FFD, 2, 1); } // odd rows
    cudaEventRecord(ev13, s2);
    { dim3 g(DD / 32, FFD / 32);
      transpose_h16<<<g, 256, 0, s2>>>(w2, w2T, FFD, DD, 1, 0); }
    cudaEventRecord(evB, s2);

    cudaStreamWaitEvent(0, evW, 0);
    // h = hidden + attn @ wo  -> fp16 residual stream (mode 4)
    gemm(attnb, woT, hidden, nullptr, nullptr, hb, nullptr, nullptr, nullptr, nullptr,
         MM, DD, DD, DD, DD, DD, DD, 4, 0);

    // y = rmsnorm(h) -> fp16 (fp16 input)
    rmsnorm_h16_in16<<<MM, 256>>>(hb, fnw, yb);

    cudaStreamWaitEvent(0, ev13, 0);
    // g = silu(y@w1) * (y@w3) -> fp16 (fused epilogue, interleaved weights)
    gemm(yb, w13T, nullptr, nullptr, nullptr, gb, nullptr, nullptr, nullptr, nullptr,
         MM, F13N, DD, DD, DD, FFD, 0, 2, 0);

    cudaStreamWaitEvent(0, evB, 0);
    // out = h + g @ w2   (fp16 residual)
    gemm(gb, w2T, nullptr, hb, out, nullptr, nullptr, nullptr, nullptr, nullptr,
         MM, DD, FFD, FFD, FFD, DD, DD, 0, 0);
}